// round 2
// baseline (speedup 1.0000x reference)
#include <cuda_runtime.h>
#include <math.h>

// Problem constants (fixed by setup_inputs): x,y [8,128,128,64] f32, blocksize 4
constexpr int B_   = 8;
constexpr int W_   = 128;
constexpr int H_   = 128;
constexpr int D_   = 64;
constexpr int BS_  = 4;
constexpr int F_   = BS_ * BS_ * D_;          // 1024 feature dim
constexpr int NROW = B_ * (W_/BS_) * (H_/BS_); // 8192 vectors per tensor
constexpr long long NX_ELEMS = (long long)B_ * W_ * H_ * D_; // 8388608

constexpr int NSPLIT = 2;

// Scratch (allocation-free rule: __device__ globals)
__device__ float g_Xn[NROW * F_];
__device__ float g_Yn[NROW * F_];
__device__ float g_pmax[NSPLIT][NROW];
__device__ int   g_pidx[NSPLIT][NROW];

// ---------------------------------------------------------------------------
// Kernel 1: combine (4x4xD block gather) + normalize (mean-center, L2)
// grid = 2*NROW blocks, 256 threads. Each block handles one 1024-d vector.
// ---------------------------------------------------------------------------
__global__ void norm_combine_kernel(const float* __restrict__ x,
                                    const float* __restrict__ y) {
    int r = blockIdx.x;
    const float* src;
    float* dst;
    if (r < NROW) { src = x; dst = g_Xn; }
    else          { r -= NROW; src = y; dst = g_Yn; }

    const int b  = r >> 10;          // r / (32*32)
    const int wb = (r >> 5) & 31;
    const int hb = r & 31;
    const int t  = threadIdx.x;

    float v[4];
#pragma unroll
    for (int j = 0; j < 4; j++) {
        int f = t + j * 256;
        int a = f >> 8;              // / (BS_*D_)
        int c = (f >> 6) & 3;        // / D_ % BS_
        int d = f & 63;
        v[j] = src[((b * W_ + wb * BS_ + a) * H_ + hb * BS_ + c) * D_ + d];
    }

    __shared__ float red[8];
    __shared__ float bcast;

    // --- mean ---
    float s = v[0] + v[1] + v[2] + v[3];
#pragma unroll
    for (int o = 16; o > 0; o >>= 1) s += __shfl_xor_sync(0xffffffffu, s, o);
    if ((t & 31) == 0) red[t >> 5] = s;
    __syncthreads();
    if (t < 32) {
        float z = (t < 8) ? red[t] : 0.0f;
#pragma unroll
        for (int o = 4; o > 0; o >>= 1) z += __shfl_xor_sync(0xffffffffu, z, o);
        if (t == 0) bcast = z;
    }
    __syncthreads();
    const float mean = bcast * (1.0f / F_);
    __syncthreads();

    // --- centered L2 norm ---
    float q = 0.0f;
#pragma unroll
    for (int j = 0; j < 4; j++) { float u = v[j] - mean; q += u * u; }
#pragma unroll
    for (int o = 16; o > 0; o >>= 1) q += __shfl_xor_sync(0xffffffffu, q, o);
    if ((t & 31) == 0) red[t >> 5] = q;
    __syncthreads();
    if (t < 32) {
        float z = (t < 8) ? red[t] : 0.0f;
#pragma unroll
        for (int o = 4; o > 0; o >>= 1) z += __shfl_xor_sync(0xffffffffu, z, o);
        if (t == 0) bcast = z;
    }
    __syncthreads();
    const float scale = 1.0f / (sqrtf(bcast) + 1e-5f);

    float* row = dst + (long long)r * F_;
#pragma unroll
    for (int j = 0; j < 4; j++) row[t + j * 256] = (v[j] - mean) * scale;
}

// ---------------------------------------------------------------------------
// Kernel 2: GEMM Xn[8192,1024] * Yn^T with fused per-row running max/argmax.
// BM=BN=64, BK=16, 256 threads, 4x4 microtile per thread.
// grid = (NROW/64, NSPLIT); each CTA scans its N-range, keeps running
// (max,idx) per row in registers of the tx==0 lanes.
// ---------------------------------------------------------------------------
#define BM 64
#define BN 64
#define BK 16

__global__ void gemm_argmax_kernel() {
    __shared__ __align__(16) float Xs[BK][BM + 4];
    __shared__ __align__(16) float Ys[BK][BN + 4];

    const int tid = threadIdx.x;
    const int tx  = tid & 15;     // N direction
    const int ty  = tid >> 4;     // M direction
    const int r0  = blockIdx.x * BM;
    const int split = blockIdx.y;
    const int nbeg = split * (NROW / NSPLIT);
    const int nend = nbeg + (NROW / NSPLIT);

    const int lrow = tid >> 2;    // 0..63 load row
    const int lkq  = tid & 3;     // 0..3  float4 slot in K

    float rmax[4];
    int   ridx[4];
#pragma unroll
    for (int i = 0; i < 4; i++) { rmax[i] = -1e30f; ridx[i] = 0; }

    for (int n0 = nbeg; n0 < nend; n0 += BN) {
        float acc[4][4];
#pragma unroll
        for (int i = 0; i < 4; i++)
#pragma unroll
            for (int j = 0; j < 4; j++) acc[i][j] = 0.0f;

        for (int k0 = 0; k0 < F_; k0 += BK) {
            float4 xa = *(const float4*)&g_Xn[(long long)(r0 + lrow) * F_ + k0 + lkq * 4];
            float4 ya = *(const float4*)&g_Yn[(long long)(n0 + lrow) * F_ + k0 + lkq * 4];
            __syncthreads();
            Xs[lkq * 4 + 0][lrow] = xa.x;
            Xs[lkq * 4 + 1][lrow] = xa.y;
            Xs[lkq * 4 + 2][lrow] = xa.z;
            Xs[lkq * 4 + 3][lrow] = xa.w;
            Ys[lkq * 4 + 0][lrow] = ya.x;
            Ys[lkq * 4 + 1][lrow] = ya.y;
            Ys[lkq * 4 + 2][lrow] = ya.z;
            Ys[lkq * 4 + 3][lrow] = ya.w;
            __syncthreads();

#pragma unroll
            for (int k = 0; k < BK; k++) {
                float4 av = *(const float4*)&Xs[k][ty * 4];
                float4 bv = *(const float4*)&Ys[k][tx * 4];
                float a[4] = {av.x, av.y, av.z, av.w};
                float bb[4] = {bv.x, bv.y, bv.z, bv.w};
#pragma unroll
                for (int i = 0; i < 4; i++)
#pragma unroll
                    for (int j = 0; j < 4; j++)
                        acc[i][j] = fmaf(a[i], bb[j], acc[i][j]);
            }
        }

        // tile epilogue: per-row max/argmax (first-max semantics: strict >,
        // tie -> lower index)
#pragma unroll
        for (int i = 0; i < 4; i++) {
            float lv = acc[i][0];
            int   li = n0 + tx * 4;
#pragma unroll
            for (int j = 1; j < 4; j++) {
                if (acc[i][j] > lv) { lv = acc[i][j]; li = n0 + tx * 4 + j; }
            }
#pragma unroll
            for (int o = 1; o < 16; o <<= 1) {
                float ov = __shfl_xor_sync(0xffffffffu, lv, o);
                int   oi = __shfl_xor_sync(0xffffffffu, li, o);
                if (ov > lv || (ov == lv && oi < li)) { lv = ov; li = oi; }
            }
            if (tx == 0) {
                if (lv > rmax[i]) { rmax[i] = lv; ridx[i] = li; }
            }
        }
    }

    if (tx == 0) {
#pragma unroll
        for (int i = 0; i < 4; i++) {
            g_pmax[split][r0 + ty * 4 + i] = rmax[i];
            g_pidx[split][r0 + ty * 4 + i] = ridx[i];
        }
    }
}

// ---------------------------------------------------------------------------
// Kernel 3: cosloss = mean(1 - rowmax)  (merge splits; split0 wins ties since
// its indices are lower)
// ---------------------------------------------------------------------------
__global__ void cosloss_kernel(float* __restrict__ out_scalar) {
    const int t = threadIdx.x;  // 1024 threads
    float s = 0.0f;
    for (int r = t; r < NROW; r += 1024) {
        float m = g_pmax[0][r];
        float m1 = g_pmax[1][r];
        if (m1 > m) m = m1;
        s += 1.0f - m;
    }
#pragma unroll
    for (int o = 16; o > 0; o >>= 1) s += __shfl_xor_sync(0xffffffffu, s, o);
    __shared__ float red[32];
    if ((t & 31) == 0) red[t >> 5] = s;
    __syncthreads();
    if (t < 32) {
        float z = red[t];
#pragma unroll
        for (int o = 16; o > 0; o >>= 1) z += __shfl_xor_sync(0xffffffffu, z, o);
        if (t == 0) *out_scalar = z * (1.0f / NROW);
    }
}

// ---------------------------------------------------------------------------
// Kernel 4: new_x gather — out[b, wb*4+a, hb*4+c, d] = Yn[argmax(r)][f]
// grid = NROW, 256 threads. float4 load from g_Yn (16B-aligned global),
// SCALAR stores to newx: the output pointer may be out+1 (scalar-first
// layout) and is only 4-byte aligned — STG.128 there traps (R1 failure).
// ---------------------------------------------------------------------------
__global__ void gather_kernel(float* __restrict__ newx) {
    const int r = blockIdx.x;
    const int b  = r >> 10;
    const int wb = (r >> 5) & 31;
    const int hb = r & 31;

    int idx = g_pidx[0][r];
    if (g_pmax[1][r] > g_pmax[0][r]) idx = g_pidx[1][r];

    const int t = threadIdx.x;
    const int f0 = t * 4;
    const int a = f0 >> 8;
    const int c = (f0 >> 6) & 3;
    const int d = f0 & 63;

    float4 val = *(const float4*)&g_Yn[(long long)idx * F_ + f0];
    long long off = ((long long)(b * W_ + wb * BS_ + a) * H_ + hb * BS_ + c) * D_ + d;
    newx[off + 0] = val.x;
    newx[off + 1] = val.y;
    newx[off + 2] = val.z;
    newx[off + 3] = val.w;
}

// ---------------------------------------------------------------------------
extern "C" void kernel_launch(void* const* d_in, const int* in_sizes, int n_in,
                              void* d_out, int out_size) {
    const float* x = (const float*)d_in[0];
    const float* y = (const float*)d_in[1];
    float* out = (float*)d_out;

    // Output layout: (cosloss scalar, new_x[8,128,128,64]) flattened in
    // reference-return order: scalar first, then new_x.
    float* newx = out;
    if ((long long)out_size > NX_ELEMS) {
        newx = out + ((long long)out_size - NX_ELEMS);
    }

    norm_combine_kernel<<<2 * NROW, 256>>>(x, y);

    dim3 ggrid(NROW / BM, NSPLIT);
    gemm_argmax_kernel<<<ggrid, 256>>>();

    if ((long long)out_size > NX_ELEMS) {
        cosloss_kernel<<<1, 1024>>>(out);
    }
    gather_kernel<<<NROW, 256>>>(newx);
}

// round 4
// speedup vs baseline: 3.1013x; 3.1013x over previous
#include <cuda_runtime.h>
#include <cuda_bf16.h>
#include <cstdint>
#include <math.h>

// Problem constants (fixed by setup_inputs): x,y [8,128,128,64] f32, blocksize 4
constexpr int B_   = 8;
constexpr int W_   = 128;
constexpr int H_   = 128;
constexpr int D_   = 64;
constexpr int BS_  = 4;
constexpr int F_   = 1024;                     // bs*bs*D feature dim
constexpr int NROW = 8192;                     // vectors per tensor
constexpr long long NX_ELEMS = (long long)B_ * W_ * H_ * D_; // 8388608

// GEMM tiling
constexpr int BM = 128;
constexpr int BN = 256;
constexpr int BK = 32;                 // bf16 elements per stage
constexpr int NTILES_N = NROW / BN;    // 32
constexpr int NTILES_M = NROW / BM;    // 64
constexpr int NSEG = 3;                // hi*hi, hi*lo, lo*hi
constexpr int NSTAGES = NSEG * (F_ / BK);  // 96

constexpr int ROWB = 80;               // padded row bytes (32 bf16 = 64B + 16 pad)
constexpr int AOFF = 0;
constexpr int BOFF = BM * ROWB;                    // 10240
constexpr int STAGE = (BM + BN) * ROWB;            // 30720
constexpr int SMEM_TOTAL = 3 * STAGE;              // 92160

// Scratch (__device__ globals; allocation-free rule)
__device__ __nv_bfloat16 g_Xh[NROW * F_];
__device__ __nv_bfloat16 g_Xl[NROW * F_];
__device__ __nv_bfloat16 g_Yh[NROW * F_];
__device__ __nv_bfloat16 g_Yl[NROW * F_];
__device__ float g_Yn[NROW * F_];
__device__ float g_pm[NTILES_N * NROW];
__device__ int   g_pi[NTILES_N * NROW];
__device__ float g_rmax[NROW];
__device__ int   g_ridx[NROW];

// ---------------------------------------------------------------------------
// helpers
// ---------------------------------------------------------------------------
__device__ __forceinline__ uint32_t smem_u32(const void* p) {
    uint32_t a;
    asm("{ .reg .u64 t; cvta.to.shared.u64 t, %1; cvt.u32.u64 %0, t; }"
        : "=r"(a) : "l"(p));
    return a;
}

#define CP16(dst, src) \
    asm volatile("cp.async.cg.shared.global [%0], [%1], 16;" \
                 :: "r"(dst), "l"(src) : "memory")

#define LDS32(v, a) \
    asm volatile("ld.shared.b32 %0, [%1];" : "=r"(v) : "r"(a))

#define MMA16816(d, a, b) \
    asm volatile("mma.sync.aligned.m16n8k16.row.col.f32.bf16.bf16.f32 " \
        "{%0,%1,%2,%3}, {%4,%5,%6,%7}, {%8,%9}, {%0,%1,%2,%3};" \
        : "+f"((d)[0]), "+f"((d)[1]), "+f"((d)[2]), "+f"((d)[3]) \
        : "r"((a)[0]), "r"((a)[1]), "r"((a)[2]), "r"((a)[3]), \
          "r"((b)[0]), "r"((b)[1]))

// ---------------------------------------------------------------------------
// Kernel 1: combine (4x4xD block gather) + normalize + bf16 hi/lo split
// ---------------------------------------------------------------------------
__global__ void norm_combine_kernel(const float* __restrict__ x,
                                    const float* __restrict__ y) {
    int r = blockIdx.x;
    const float* src;
    bool isx;
    if (r < NROW) { src = x; isx = true; }
    else          { r -= NROW; src = y; isx = false; }

    const int b  = r >> 10;
    const int wb = (r >> 5) & 31;
    const int hb = r & 31;
    const int t  = threadIdx.x;

    float v[4];
#pragma unroll
    for (int j = 0; j < 4; j++) {
        int f = t + j * 256;
        int a = f >> 8;
        int c = (f >> 6) & 3;
        int d = f & 63;
        v[j] = src[((b * W_ + wb * BS_ + a) * H_ + hb * BS_ + c) * D_ + d];
    }

    __shared__ float red[8];
    __shared__ float bcast;

    float s = v[0] + v[1] + v[2] + v[3];
#pragma unroll
    for (int o = 16; o > 0; o >>= 1) s += __shfl_xor_sync(0xffffffffu, s, o);
    if ((t & 31) == 0) red[t >> 5] = s;
    __syncthreads();
    if (t < 32) {
        float z = (t < 8) ? red[t] : 0.0f;
#pragma unroll
        for (int o = 4; o > 0; o >>= 1) z += __shfl_xor_sync(0xffffffffu, z, o);
        if (t == 0) bcast = z;
    }
    __syncthreads();
    const float mean = bcast * (1.0f / F_);
    __syncthreads();

    float q = 0.0f;
#pragma unroll
    for (int j = 0; j < 4; j++) { float u = v[j] - mean; q += u * u; }
#pragma unroll
    for (int o = 16; o > 0; o >>= 1) q += __shfl_xor_sync(0xffffffffu, q, o);
    if ((t & 31) == 0) red[t >> 5] = q;
    __syncthreads();
    if (t < 32) {
        float z = (t < 8) ? red[t] : 0.0f;
#pragma unroll
        for (int o = 4; o > 0; o >>= 1) z += __shfl_xor_sync(0xffffffffu, z, o);
        if (t == 0) bcast = z;
    }
    __syncthreads();
    const float scale = 1.0f / (sqrtf(bcast) + 1e-5f);

    long long base = (long long)r * F_;
#pragma unroll
    for (int j = 0; j < 4; j++) {
        float w  = (v[j] - mean) * scale;
        __nv_bfloat16 hi = __float2bfloat16(w);
        __nv_bfloat16 lo = __float2bfloat16(w - __bfloat162float(hi));
        long long o = base + t + j * 256;
        if (isx) { g_Xh[o] = hi; g_Xl[o] = lo; }
        else     { g_Yh[o] = hi; g_Yl[o] = lo; g_Yn[o] = w; }
    }
}

// ---------------------------------------------------------------------------
// Kernel 2: bf16 mma.sync GEMM tile (128x256) over K=3x1024 (3-product
// split), fused per-row max/argmax partials.
// 8 warps = 2(M) x 4(N), 64x64 per warp. 3-stage cp.async pipeline.
// ---------------------------------------------------------------------------
__global__ void __launch_bounds__(256, 1) gemm_argmax_mma() {
    extern __shared__ __align__(128) char smem[];
    const uint32_t sb = smem_u32(smem);

    const int tid  = threadIdx.x;
    const int wid  = tid >> 5;
    const int lane = tid & 31;
    const int mw   = wid >> 2;          // 0..1
    const int nw   = wid & 3;           // 0..3
    const int n0   = blockIdx.x * BN;
    const int r0   = blockIdx.y * BM;

    float acc[4][8][4];
#pragma unroll
    for (int mt = 0; mt < 4; mt++)
#pragma unroll
        for (int nt = 0; nt < 8; nt++)
#pragma unroll
            for (int k = 0; k < 4; k++) acc[mt][nt][k] = 0.0f;

    // ---- stage issue ----
    auto issue = [&](int s) {
        const int seg = s >> 5;
        const int k0  = (s & 31) * BK;
        const __nv_bfloat16* __restrict__ As = (seg == 2) ? g_Xl : g_Xh;
        const __nv_bfloat16* __restrict__ Bs = (seg == 1) ? g_Yl : g_Yh;
        const uint32_t base = sb + (s % 3) * STAGE;
#pragma unroll
        for (int j = 0; j < 2; j++) {                // A: 128 rows x 4 chunks
            int idx = tid + j * 256;
            int m = idx >> 2, ch = idx & 3;
            CP16(base + AOFF + m * ROWB + ch * 16,
                 As + (long long)(r0 + m) * F_ + k0 + ch * 8);
        }
#pragma unroll
        for (int j = 0; j < 4; j++) {                // B: 256 rows x 4 chunks
            int idx = tid + j * 256;
            int n = idx >> 2, ch = idx & 3;
            CP16(base + BOFF + n * ROWB + ch * 16,
                 Bs + (long long)(n0 + n) * F_ + k0 + ch * 8);
        }
        asm volatile("cp.async.commit_group;" ::: "memory");
    };

    issue(0);
    issue(1);

    const uint32_t arow = (uint32_t)(mw * 64 + (lane >> 2)) * ROWB + (lane & 3) * 4;
    const uint32_t brow = (uint32_t)(nw * 64 + (lane >> 2)) * ROWB + (lane & 3) * 4;

    for (int s = 0; s < NSTAGES; s++) {
        asm volatile("cp.async.wait_group 1;" ::: "memory");
        __syncthreads();
        if (s + 2 < NSTAGES) issue(s + 2);

        const uint32_t Ab = sb + (s % 3) * STAGE + AOFF;
        const uint32_t Bb = sb + (s % 3) * STAGE + BOFF;

#pragma unroll
        for (int ks = 0; ks < 2; ks++) {
            // A fragments: a0=(r,klo) a1=(r+8,klo) a2=(r,khi) a3=(r+8,khi)
            uint32_t af[4][4];
#pragma unroll
            for (int mt = 0; mt < 4; mt++) {
                uint32_t a0 = Ab + arow + mt * (16 * ROWB) + ks * 32;
                LDS32(af[mt][0], a0);
                LDS32(af[mt][1], a0 + 8 * ROWB);
                LDS32(af[mt][2], a0 + 16);
                LDS32(af[mt][3], a0 + 8 * ROWB + 16);
            }
            uint32_t bf_[8][2];
#pragma unroll
            for (int nt = 0; nt < 8; nt++) {
                uint32_t b0 = Bb + brow + nt * (8 * ROWB) + ks * 32;
                LDS32(bf_[nt][0], b0);
                LDS32(bf_[nt][1], b0 + 16);
            }
#pragma unroll
            for (int mt = 0; mt < 4; mt++)
#pragma unroll
                for (int nt = 0; nt < 8; nt++)
                    MMA16816(acc[mt][nt], af[mt], bf_[nt]);
        }
    }
    __syncthreads();

    // ---- per-row max/argmax within tile (first-max tie rules) ----
    __shared__ float redv[4][BM];
    __shared__ int   redi[4][BM];

#pragma unroll
    for (int mt = 0; mt < 4; mt++) {
#pragma unroll
        for (int h = 0; h < 2; h++) {
            float bv = -1e30f;
            int   bi = 0;
#pragma unroll
            for (int nt = 0; nt < 8; nt++) {
#pragma unroll
                for (int c = 0; c < 2; c++) {
                    float v = acc[mt][nt][h * 2 + c];
                    int gc = n0 + nw * 64 + nt * 8 + (lane & 3) * 2 + c;
                    if (v > bv || (v == bv && gc < bi)) { bv = v; bi = gc; }
                }
            }
#pragma unroll
            for (int o = 1; o < 4; o <<= 1) {
                float ov = __shfl_xor_sync(0xffffffffu, bv, o);
                int   oi = __shfl_xor_sync(0xffffffffu, bi, o);
                if (ov > bv || (ov == bv && oi < bi)) { bv = ov; bi = oi; }
            }
            if ((lane & 3) == 0) {
                int rl = mw * 64 + mt * 16 + h * 8 + (lane >> 2);
                redv[nw][rl] = bv;
                redi[nw][rl] = bi;
            }
        }
    }
    __syncthreads();

    if (tid < BM) {
        float bv = redv[0][tid];
        int   bi = redi[0][tid];
#pragma unroll
        for (int w = 1; w < 4; w++) {
            float v = redv[w][tid];
            int   i = redi[w][tid];
            if (v > bv || (v == bv && i < bi)) { bv = v; bi = i; }
        }
        g_pm[blockIdx.x * NROW + r0 + tid] = bv;
        g_pi[blockIdx.x * NROW + r0 + tid] = bi;
    }
}

// ---------------------------------------------------------------------------
// Kernel 3: fold N-tile partials per row (ascending tile order = first-max)
// ---------------------------------------------------------------------------
__global__ void reduce_kernel() {
    int r = blockIdx.x * 256 + threadIdx.x;
    float bv = g_pm[r];
    int   bi = g_pi[r];
    for (int nt = 1; nt < NTILES_N; nt++) {
        float v = g_pm[nt * NROW + r];
        int   i = g_pi[nt * NROW + r];
        if (v > bv || (v == bv && i < bi)) { bv = v; bi = i; }
    }
    g_rmax[r] = bv;
    g_ridx[r] = bi;
}

// ---------------------------------------------------------------------------
// Kernel 4: cosloss = mean(1 - rowmax)
// ---------------------------------------------------------------------------
__global__ void cosloss_kernel(float* __restrict__ out_scalar) {
    const int t = threadIdx.x;
    float s = 0.0f;
    for (int r = t; r < NROW; r += 1024) s += 1.0f - g_rmax[r];
#pragma unroll
    for (int o = 16; o > 0; o >>= 1) s += __shfl_xor_sync(0xffffffffu, s, o);
    __shared__ float red[32];
    if ((t & 31) == 0) red[t >> 5] = s;
    __syncthreads();
    if (t < 32) {
        float z = red[t];
#pragma unroll
        for (int o = 16; o > 0; o >>= 1) z += __shfl_xor_sync(0xffffffffu, z, o);
        if (t == 0) *out_scalar = z * (1.0f / NROW);
    }
}

// ---------------------------------------------------------------------------
// Kernel 5: new_x gather (scalar stores: out pointer may be 4B-aligned only)
// ---------------------------------------------------------------------------
__global__ void gather_kernel(float* __restrict__ newx) {
    const int r  = blockIdx.x;
    const int b  = r >> 10;
    const int wb = (r >> 5) & 31;
    const int hb = r & 31;

    const int idx = g_ridx[r];

    const int t  = threadIdx.x;
    const int f0 = t * 4;
    const int a  = f0 >> 8;
    const int c  = (f0 >> 6) & 3;
    const int d  = f0 & 63;

    float4 val = *(const float4*)&g_Yn[(long long)idx * F_ + f0];
    long long off = ((long long)(b * W_ + wb * BS_ + a) * H_ + hb * BS_ + c) * D_ + d;
    newx[off + 0] = val.x;
    newx[off + 1] = val.y;
    newx[off + 2] = val.z;
    newx[off + 3] = val.w;
}

// ---------------------------------------------------------------------------
extern "C" void kernel_launch(void* const* d_in, const int* in_sizes, int n_in,
                              void* d_out, int out_size) {
    const float* x = (const float*)d_in[0];
    const float* y = (const float*)d_in[1];
    float* out = (float*)d_out;

    float* newx = out;
    if ((long long)out_size > NX_ELEMS) {
        newx = out + ((long long)out_size - NX_ELEMS);
    }

    static bool attr_set = false;
    if (!attr_set) {
        cudaFuncSetAttribute(gemm_argmax_mma,
                             cudaFuncAttributeMaxDynamicSharedMemorySize, SMEM_TOTAL);
        attr_set = true;
    }

    norm_combine_kernel<<<2 * NROW, 256>>>(x, y);

    dim3 ggrid(NTILES_N, NTILES_M);
    gemm_argmax_mma<<<ggrid, 256, SMEM_TOTAL>>>();

    reduce_kernel<<<NROW / 256, 256>>>();

    if ((long long)out_size > NX_ELEMS) {
        cosloss_kernel<<<1, 1024>>>(out);
    }
    gather_kernel<<<NROW, 256>>>(newx);
}